// round 11
// baseline (speedup 1.0000x reference)
#include <cuda_runtime.h>

#define NN 16384
#define DEG 20
typedef unsigned long long u64;

__device__ float g_qt[NN * 32];

static __device__ __forceinline__ u64 pk2(float lo, float hi) {
    u64 r; asm("mov.b64 %0, {%1, %2};" : "=l"(r) : "f"(lo), "f"(hi)); return r;
}
static __device__ __forceinline__ void upk2(u64 v, float& lo, float& hi) {
    asm("mov.b64 {%0, %1}, %2;" : "=f"(lo), "=f"(hi) : "l"(v));
}
static __device__ __forceinline__ u64 f2(u64 a, u64 b, u64 c) {
    u64 d; asm("fma.rn.f32x2 %0, %1, %2, %3;" : "=l"(d) : "l"(a), "l"(b), "l"(c)); return d;
}
static __device__ __forceinline__ u64 mul2(u64 a, u64 b) {
    u64 d; asm("mul.rn.f32x2 %0, %1, %2;" : "=l"(d) : "l"(a), "l"(b)); return d;
}
static __device__ __forceinline__ u64 add2(u64 a, u64 b) {
    u64 d; asm("add.rn.f32x2 %0, %1, %2;" : "=l"(d) : "l"(a), "l"(b)); return d;
}
static __device__ __forceinline__ float ss(float x) {
    return x > 0.f ? __expf(__fdividef(-1.f, x)) : 0.f;
}
static __device__ __forceinline__ float bsum(float v) {
#pragma unroll
    for (int o = 16; o >= 1; o >>= 1) v += __shfl_xor_sync(0xffffffffu, v, o);
    return v;
}

// ---------------- K0: fold Wq@Wd/sqrt(8) into per-node query ----------------
__global__ void k0_qt(const float* __restrict__ f, const float* __restrict__ Wq_s,
                      const float* __restrict__ Wq_v, const float* __restrict__ Wd_s,
                      const float* __restrict__ Wd_v) {
    __shared__ float As[64], Av[64];
    int t = threadIdx.x;
    if (t < 64) {
        int m = t >> 3, j = t & 7;
        float s = 0.f, v = 0.f;
#pragma unroll
        for (int o = 0; o < 8; o++) {
            s = fmaf(Wq_s[m * 8 + o], Wd_s[o * 8 + j], s);
            v = fmaf(Wq_v[m * 8 + o], Wd_v[o * 8 + j], v);
        }
        As[t] = s * 0.35355339059327373f;
        Av[t] = v * 0.35355339059327373f;
    }
    __syncthreads();
    int n = blockIdx.x * 256 + t;
    float fs[8], fv[24];
#pragma unroll
    for (int m = 0; m < 8; m++) fs[m] = f[n * 32 + m];
#pragma unroll
    for (int m = 0; m < 24; m++) fv[m] = f[n * 32 + 8 + m];
#pragma unroll
    for (int j = 0; j < 8; j++) {
        float s = 0.f;
#pragma unroll
        for (int m = 0; m < 8; m++) s = fmaf(fs[m], As[m * 8 + j], s);
        g_qt[n * 32 + j] = s;
    }
#pragma unroll
    for (int j = 0; j < 8; j++) {
        float v0 = 0.f, v1 = 0.f, v2 = 0.f;
#pragma unroll
        for (int m = 0; m < 8; m++) {
            float a = Av[m * 8 + j];
            v0 = fmaf(fv[m * 3 + 0], a, v0);
            v1 = fmaf(fv[m * 3 + 1], a, v1);
            v2 = fmaf(fv[m * 3 + 2], a, v2);
        }
        g_qt[n * 32 + 8 + j * 3 + 0] = v0;
        g_qt[n * 32 + 8 + j * 3 + 1] = v1;
        g_qt[n * 32 + 8 + j * 3 + 2] = v2;
    }
}

// smem: W2 as u64 [64][129] (16512 fl) | W1 640 fl | 13 node scratch
#define SM_W1 16512
#define SM_NS 17152
#define NS_STR 1872
#define F_OFF   0     // [64][24] rows: gs(0-7) gd(8-15) su(16-39) gv(40-63)
#define EMB_OFF 1536  // [10][24]
#define LC_OFF  1776
#define LG_OFF  1796
#define CO_OFF  1816
#define QV_OFF  1840  // [3][4] u64 = 24 floats, 16B aligned
#define QQ_OFF  1864  // [4] u64 = 8 floats, 16B aligned
#define NTPB 416
#define NODES_PB 13
#define SMEM_BYTES ((SM_NS + NODES_PB * NS_STR) * 4)

static __device__ __forceinline__ void stage(float* sm, const float* W2,
                                             const float* W1, int tid) {
    u64* d = (u64*)sm;
    const u64* s = (const u64*)W2;
    for (int idx = tid; idx < 8192; idx += NTPB)
        d[(idx >> 7) * 129 + (idx & 127)] = s[idx];
    float* w1d = sm + SM_W1;
    for (int i = tid; i < 640; i += NTPB) w1d[i] = W1[i];
}

// h pairs over 20 edges for hidden unit t (folds /sqrt(10), silu, /8)
static __device__ __forceinline__ void fc1_row(const float* ws, const float* W1s,
                                               int t, u64* h) {
    u64 acc[10];
    {
        float w = W1s[t];
        u64 wd = pk2(w, w);
        const ulonglong2* Er = (const ulonglong2*)(ws + EMB_OFF);
#pragma unroll
        for (int m = 0; m < 5; m++) {
            ulonglong2 p = Er[m];
            acc[2 * m] = mul2(wd, p.x);
            acc[2 * m + 1] = mul2(wd, p.y);
        }
    }
#pragma unroll
    for (int b = 1; b < 10; b++) {
        float w = W1s[b * 64 + t];
        u64 wd = pk2(w, w);
        const ulonglong2* Er = (const ulonglong2*)(ws + EMB_OFF + b * 24);
#pragma unroll
        for (int m = 0; m < 5; m++) {
            ulonglong2 p = Er[m];
            acc[2 * m] = f2(wd, p.x, acc[2 * m]);
            acc[2 * m + 1] = f2(wd, p.y, acc[2 * m + 1]);
        }
    }
#pragma unroll
    for (int m = 0; m < 10; m++) {
        float a0, a1;
        upk2(acc[m], a0, a1);
        a0 *= 0.31622776601683794f;
        a1 *= 0.31622776601683794f;
        h[m] = pk2(__fdividef(a0, 1.f + __expf(-a0)) * 0.125f,
                   __fdividef(a1, 1.f + __expf(-a1)) * 0.125f);
    }
}

static __device__ __forceinline__ void dupd(const float* ws, int xi, float M, u64* D) {
    u64 Md = pk2(M, M);
    const ulonglong2* Fr = (const ulonglong2*)(ws + F_OFF + xi * 24);
#pragma unroll
    for (int m = 0; m < 5; m++) {
        ulonglong2 p = Fr[m];
        D[2 * m] = f2(Md, p.x, D[2 * m]);
        D[2 * m + 1] = f2(Md, p.y, D[2 * m + 1]);
    }
}

static __device__ __forceinline__ float srow(const float* ws, int xi, const u64* hp) {
    const ulonglong2* Fr = (const ulonglong2*)(ws + F_OFF + xi * 24);
    u64 s0 = 0ULL, s1 = 0ULL;
#pragma unroll
    for (int m = 0; m < 5; m++) {
        ulonglong2 p = Fr[m];
        s0 = f2(hp[2 * m], p.x, s0);
        s1 = f2(hp[2 * m + 1], p.y, s1);
    }
    float lo, hi;
    upk2(add2(s0, s1), lo, hi);
    return lo + hi;
}

// dot8 against a q vector held in smem (volatile: keep q out of registers)
static __device__ __forceinline__ float dot8sh(u64 w0, u64 w1, u64 w2, u64 w3,
                                               unsigned qsh) {
    u64 q0, q1, q2, q3;
    asm volatile("ld.shared.v2.u64 {%0, %1}, [%2];"
                 : "=l"(q0), "=l"(q1) : "r"(qsh));
    asm volatile("ld.shared.v2.u64 {%0, %1}, [%2];"
                 : "=l"(q2), "=l"(q3) : "r"(qsh + 16));
    u64 p0 = mul2(w0, q0);
    p0 = f2(w1, q1, p0);
    u64 p1 = mul2(w2, q2);
    p1 = f2(w3, q3, p1);
    float lo, hi;
    upk2(add2(p0, p1), lo, hi);
    return lo + hi;
}

__global__ __launch_bounds__(NTPB, 1) void se3_main(
    const float* __restrict__ f, const float* __restrict__ pos,
    const float* __restrict__ Wk1, const float* __restrict__ Wk2,
    const float* __restrict__ Wv1, const float* __restrict__ Wv2,
    const int* __restrict__ edge_src, float* __restrict__ out) {
    extern __shared__ float sm[];
    const int tid = threadIdx.x;
    const int wid = tid >> 5, lane = tid & 31;
    const int n = blockIdx.x * NODES_PB + wid;
    const bool active = (n < NN);
    float* ws = sm + SM_NS + wid * NS_STR;
    const u64* W2s64 = (const u64*)sm;
    const float* W1s = sm + SM_W1;

    // ---- setup: lanes 0-19 = edges; lanes 20-22 pack qv; lane 23 packs qq ----
    if (active) {
        if (lane < 20) {
            int e = lane;
            int src = edge_src[n * DEG + e];
            float dx = pos[src * 3 + 0] - pos[n * 3 + 0];
            float dy = pos[src * 3 + 1] - pos[n * 3 + 1];
            float dz = pos[src * 3 + 2] - pos[n * 3 + 2];
            float r2 = fmaf(dx, dx, fmaf(dy, dy, dz * dz));
            float ir = rsqrtf(r2);
            float r = r2 * ir;
            float uu[3] = {dx * ir, dy * ir, dz * ir};
            const float4* fp = (const float4*)(f + src * 32);
            float4 s0 = fp[0], s1 = fp[1];
            float gs[8] = {s0.x, s0.y, s0.z, s0.w, s1.x, s1.y, s1.z, s1.w};
            float gv[24];
            {
                float4 v0 = fp[2], v1 = fp[3], v2 = fp[4];
                float4 v3 = fp[5], v4 = fp[6], v5 = fp[7];
                gv[0]=v0.x; gv[1]=v0.y; gv[2]=v0.z; gv[3]=v0.w;
                gv[4]=v1.x; gv[5]=v1.y; gv[6]=v1.z; gv[7]=v1.w;
                gv[8]=v2.x; gv[9]=v2.y; gv[10]=v2.z; gv[11]=v2.w;
                gv[12]=v3.x; gv[13]=v3.y; gv[14]=v3.z; gv[15]=v3.w;
                gv[16]=v4.x; gv[17]=v4.y; gv[18]=v4.z; gv[19]=v4.w;
                gv[20]=v5.x; gv[21]=v5.y; gv[22]=v5.z; gv[23]=v5.w;
            }
            float* Ff = ws + F_OFF;
#pragma unroll
            for (int i = 0; i < 8; i++) {
                float gsi = gs[i];
                float g0 = gv[3 * i + 0], g1 = gv[3 * i + 1], g2 = gv[3 * i + 2];
                Ff[i * 24 + e] = gsi;
                Ff[(8 + i) * 24 + e] = fmaf(g0, uu[0], fmaf(g1, uu[1], g2 * uu[2]));
                Ff[(16 + i * 3 + 0) * 24 + e] = gsi * uu[0];
                Ff[(16 + i * 3 + 1) * 24 + e] = gsi * uu[1];
                Ff[(16 + i * 3 + 2) * 24 + e] = gsi * uu[2];
                Ff[(40 + i * 3 + 0) * 24 + e] = g0;
                Ff[(40 + i * 3 + 1) * 24 + e] = g1;
                Ff[(40 + i * 3 + 2) * 24 + e] = g2;
            }
            float rr = r * (11.0f / 3.5f);
#pragma unroll
            for (int b = 0; b < 10; b++) {
                float d = rr - (float)(b + 1);
                ws[EMB_OFF + b * 24 + e] = 26.66929f * ss(d + 1.f) * ss(1.f - d);
            }
            float x = 10.f * (1.f - r * (1.f / 3.5f));
            ws[LC_OFF + e] = (x > 0.f) ? -__fdividef(1.f, x) : -1e30f;
        } else if (lane < 23) {
            int c = lane - 20;
            const float* qf = g_qt + n * 32 + 8;
            u64* qd = (u64*)(ws + QV_OFF) + c * 4;
#pragma unroll
            for (int m = 0; m < 4; m++)
                qd[m] = pk2(qf[(2 * m) * 3 + c], qf[(2 * m + 1) * 3 + c]);
        } else if (lane == 23) {
            const u64* qsp = (const u64*)(g_qt + n * 32);
            u64* qd = (u64*)(ws + QQ_OFF);
#pragma unroll
            for (int m = 0; m < 4; m++) qd[m] = qsp[m];
        }
    }
    stage(sm, Wk2, Wk1, tid);
    __syncthreads();

    const unsigned qv_sh = (unsigned)__cvta_generic_to_shared(ws + QV_OFF);
    const unsigned qq_sh = (unsigned)__cvta_generic_to_shared(ws + QQ_OFF);
    const unsigned co_sh = (unsigned)__cvta_generic_to_shared(ws + CO_OFF);

    // ============ PASS 0: k-net -> logits -> coef ============
    if (active) {
        u64 Lacc[10];
#pragma unroll
        for (int m = 0; m < 10; m++) Lacc[m] = 0ULL;

#pragma unroll 1
        for (int half = 0; half < 2; half++) {
            int t = half * 32 + lane;
            u64 h[10], D[10];
            fc1_row(ws, W1s, t, h);
#pragma unroll
            for (int m = 0; m < 10; m++) D[m] = 0ULL;
            const u64* wrow = W2s64 + t * 129;
            // paths 0,1 (xi = pi): M[2] batches, qq from smem
#pragma unroll 1
            for (int g = 0; g < 8; g++) {
                const u64* wk0 = wrow + (2 * g) * 4;
                const u64* wk1 = wrow + (2 * g + 1) * 4;
                float M0 = dot8sh(wk0[0], wk0[1], wk0[2], wk0[3], qq_sh);
                float M1 = dot8sh(wk1[0], wk1[1], wk1[2], wk1[3], qq_sh);
                dupd(ws, 2 * g, M0, D);
                dupd(ws, 2 * g + 1, M1, D);
            }
            // paths 2,3: qv from smem
#pragma unroll 1
            for (int pi = 0; pi < 16; pi++) {
                const u64* wk = wrow + 64 + pi * 4;
                u64 w0 = wk[0], w1 = wk[1], w2 = wk[2], w3 = wk[3];
                int xb = 16 + (pi >> 3) * 24 + (pi & 7) * 3;
                float sc = (pi >= 8) ? 0.5773502691896258f : 1.0f;
#pragma unroll
                for (int c = 0; c < 3; c++)
                    dupd(ws, xb + c,
                         dot8sh(w0, w1, w2, w3, qv_sh + c * 32) * sc, D);
            }
#pragma unroll
            for (int m = 0; m < 10; m++) Lacc[m] = f2(h[m], D[m], Lacc[m]);
        }
#pragma unroll
        for (int o = 16; o >= 1; o >>= 1)
#pragma unroll
            for (int m = 0; m < 10; m++)
                Lacc[m] = add2(Lacc[m], __shfl_xor_sync(0xffffffffu, Lacc[m], o));
        if (lane == 0) {
            u64* Lg = (u64*)(ws + LG_OFF);
#pragma unroll
            for (int m = 0; m < 10; m++) Lg[m] = Lacc[m];
        }
        __syncwarp();
        {
            float L = -3.0e38f;
            if (lane < 20)
                L = fmaf(0.022097086912079608f, ws[LG_OFF + lane], ws[LC_OFF + lane]);
            float M = L;
#pragma unroll
            for (int o = 16; o >= 1; o >>= 1)
                M = fmaxf(M, __shfl_xor_sync(0xffffffffu, M, o));
            float ex = (lane < 20) ? __expf(L - M) : 0.f;
            float z = bsum(ex);
            if (lane < 20)
                ws[CO_OFF + lane] = 0.25f * sqrtf(__fdividef(ex, z) + 1e-12f);
        }
        __syncwarp();
    }

    __syncthreads();
    stage(sm, Wv2, Wv1, tid);
    __syncthreads();

    // ============ PASS 1: v-net -> outputs ============
    if (active) {
        u64 os[4] = {0ULL, 0ULL, 0ULL, 0ULL};
        u64 ov[3][4] = {};

#pragma unroll 1
        for (int half = 0; half < 2; half++) {
            int t = half * 32 + lane;
            u64 h[10];
            fc1_row(ws, W1s, t, h);
            // scale by coef from smem (volatile: keep co out of registers)
#pragma unroll
            for (int m = 0; m < 10; m++) {
                u64 cm;
                asm volatile("ld.shared.b64 %0, [%1];"
                             : "=l"(cm) : "r"(co_sh + m * 8));
                h[m] = mul2(h[m], cm);
            }
            const u64* wrow = W2s64 + t * 129;
            // paths 0,1 -> out_s: S[2] batches
#pragma unroll 1
            for (int g = 0; g < 8; g++) {
                float S0 = srow(ws, 2 * g, h);
                float S1 = srow(ws, 2 * g + 1, h);
                u64 Sd0 = pk2(S0, S0), Sd1 = pk2(S1, S1);
                const u64* wk0 = wrow + (2 * g) * 4;
                const u64* wk1 = wrow + (2 * g + 1) * 4;
#pragma unroll
                for (int r = 0; r < 4; r++) os[r] = f2(Sd0, wk0[r], os[r]);
#pragma unroll
                for (int r = 0; r < 4; r++) os[r] = f2(Sd1, wk1[r], os[r]);
            }
            // paths 2,3 -> out_v
#pragma unroll 1
            for (int pi = 0; pi < 16; pi++) {
                const u64* wk = wrow + 64 + pi * 4;
                u64 w0 = wk[0], w1 = wk[1], w2 = wk[2], w3 = wk[3];
                int xb = 16 + (pi >> 3) * 24 + (pi & 7) * 3;
                float sc = (pi < 8) ? 1.7320508075688772f : 1.0f;
#pragma unroll
                for (int c = 0; c < 3; c++) {
                    float S = srow(ws, xb + c, h) * sc;
                    u64 Sd = pk2(S, S);
                    ov[c][0] = f2(Sd, w0, ov[c][0]);
                    ov[c][1] = f2(Sd, w1, ov[c][1]);
                    ov[c][2] = f2(Sd, w2, ov[c][2]);
                    ov[c][3] = f2(Sd, w3, ov[c][3]);
                }
            }
        }
#pragma unroll
        for (int o = 16; o >= 1; o >>= 1) {
#pragma unroll
            for (int r = 0; r < 4; r++)
                os[r] = add2(os[r], __shfl_xor_sync(0xffffffffu, os[r], o));
#pragma unroll
            for (int c = 0; c < 3; c++)
#pragma unroll
                for (int r = 0; r < 4; r++)
                    ov[c][r] = add2(ov[c][r], __shfl_xor_sync(0xffffffffu, ov[c][r], o));
        }
        if (lane < 4) {
            float a, b;
            upk2(os[lane], a, b);
            out[n * 32 + 2 * lane] = a;
            out[n * 32 + 2 * lane + 1] = b;
        } else if (lane < 16) {
            int idx = lane - 4;
            int c = idx >> 2, r = idx & 3;
            float a, b;
            upk2(ov[c][r], a, b);
            out[n * 32 + 8 + (2 * r) * 3 + c] = a;
            out[n * 32 + 8 + (2 * r + 1) * 3 + c] = b;
        }
    }
}

extern "C" void kernel_launch(void* const* d_in, const int* in_sizes, int n_in,
                              void* d_out, int out_size) {
    const float* f    = (const float*)d_in[0];
    const float* pos  = (const float*)d_in[1];
    const float* Wq_s = (const float*)d_in[2];
    const float* Wq_v = (const float*)d_in[3];
    const float* Wk1  = (const float*)d_in[4];
    const float* Wk2  = (const float*)d_in[5];
    const float* Wv1  = (const float*)d_in[6];
    const float* Wv2  = (const float*)d_in[7];
    const float* Wd_s = (const float*)d_in[8];
    const float* Wd_v = (const float*)d_in[9];
    const int* esrc   = (const int*)d_in[10];
    float* out = (float*)d_out;

    cudaFuncSetAttribute(se3_main, cudaFuncAttributeMaxDynamicSharedMemorySize, SMEM_BYTES);
    k0_qt<<<64, 256>>>(f, Wq_s, Wq_v, Wd_s, Wd_v);
    se3_main<<<(NN + NODES_PB - 1) / NODES_PB, NTPB, SMEM_BYTES>>>(
        f, pos, Wk1, Wk2, Wv1, Wv2, esrc, out);
}

// round 12
// speedup vs baseline: 1.2991x; 1.2991x over previous
#include <cuda_runtime.h>

#define NN 16384
#define DEG 20
typedef unsigned long long u64;

__device__ float g_qt[NN * 32];

static __device__ __forceinline__ u64 pk2(float lo, float hi) {
    u64 r; asm("mov.b64 %0, {%1, %2};" : "=l"(r) : "f"(lo), "f"(hi)); return r;
}
static __device__ __forceinline__ void upk2(u64 v, float& lo, float& hi) {
    asm("mov.b64 {%0, %1}, %2;" : "=f"(lo), "=f"(hi) : "l"(v));
}
static __device__ __forceinline__ u64 f2(u64 a, u64 b, u64 c) {
    u64 d; asm("fma.rn.f32x2 %0, %1, %2, %3;" : "=l"(d) : "l"(a), "l"(b), "l"(c)); return d;
}
static __device__ __forceinline__ u64 mul2(u64 a, u64 b) {
    u64 d; asm("mul.rn.f32x2 %0, %1, %2;" : "=l"(d) : "l"(a), "l"(b)); return d;
}
static __device__ __forceinline__ u64 add2(u64 a, u64 b) {
    u64 d; asm("add.rn.f32x2 %0, %1, %2;" : "=l"(d) : "l"(a), "l"(b)); return d;
}
static __device__ __forceinline__ float ss(float x) {
    return x > 0.f ? __expf(__fdividef(-1.f, x)) : 0.f;
}
static __device__ __forceinline__ float bsum(float v) {
#pragma unroll
    for (int o = 16; o >= 1; o >>= 1) v += __shfl_xor_sync(0xffffffffu, v, o);
    return v;
}

// ---------------- K0: fold Wq@Wd/sqrt(8) into per-node query ----------------
__global__ void k0_qt(const float* __restrict__ f, const float* __restrict__ Wq_s,
                      const float* __restrict__ Wq_v, const float* __restrict__ Wd_s,
                      const float* __restrict__ Wd_v) {
    __shared__ float As[64], Av[64];
    int t = threadIdx.x;
    if (t < 64) {
        int m = t >> 3, j = t & 7;
        float s = 0.f, v = 0.f;
#pragma unroll
        for (int o = 0; o < 8; o++) {
            s = fmaf(Wq_s[m * 8 + o], Wd_s[o * 8 + j], s);
            v = fmaf(Wq_v[m * 8 + o], Wd_v[o * 8 + j], v);
        }
        As[t] = s * 0.35355339059327373f;
        Av[t] = v * 0.35355339059327373f;
    }
    __syncthreads();
    int n = blockIdx.x * 256 + t;
    float fs[8], fv[24];
#pragma unroll
    for (int m = 0; m < 8; m++) fs[m] = f[n * 32 + m];
#pragma unroll
    for (int m = 0; m < 24; m++) fv[m] = f[n * 32 + 8 + m];
#pragma unroll
    for (int j = 0; j < 8; j++) {
        float s = 0.f;
#pragma unroll
        for (int m = 0; m < 8; m++) s = fmaf(fs[m], As[m * 8 + j], s);
        g_qt[n * 32 + j] = s;
    }
#pragma unroll
    for (int j = 0; j < 8; j++) {
        float v0 = 0.f, v1 = 0.f, v2 = 0.f;
#pragma unroll
        for (int m = 0; m < 8; m++) {
            float a = Av[m * 8 + j];
            v0 = fmaf(fv[m * 3 + 0], a, v0);
            v1 = fmaf(fv[m * 3 + 1], a, v1);
            v2 = fmaf(fv[m * 3 + 2], a, v2);
        }
        g_qt[n * 32 + 8 + j * 3 + 0] = v0;
        g_qt[n * 32 + 8 + j * 3 + 1] = v1;
        g_qt[n * 32 + 8 + j * 3 + 2] = v2;
    }
}

// smem: W2k u64[64][129] | W2v u64[64][129] | W1k 640 | W1v 640 | 12 node scratch
#define SM_W2V 16512
#define SM_W1K 33024
#define SM_W1V 33664
#define SM_NS  34304
#define NS_STR 1864
#define F_OFF   0     // [64][24] rows: gs(0-7) gd(8-15) su(16-39) gv(40-63)
#define EMB_OFF 1536  // [10][24]
#define LC_OFF  1776
#define LG_OFF  1796
#define CO_OFF  1816
#define QV_OFF  1840  // [3][4] u64 = 24 floats, 16B aligned
#define NTPB 384
#define NODES_PB 12
#define SMEM_BYTES ((SM_NS + NODES_PB * NS_STR) * 4)

// stage both nets once
static __device__ __forceinline__ void stage_all(float* sm, const float* Wk2,
                                                 const float* Wv2, const float* Wk1,
                                                 const float* Wv1, int tid) {
    u64* dk = (u64*)sm;
    u64* dv = (u64*)(sm + SM_W2V);
    const u64* sk = (const u64*)Wk2;
    const u64* sv = (const u64*)Wv2;
    for (int idx = tid; idx < 8192; idx += NTPB) {
        int o = (idx >> 7) * 129 + (idx & 127);
        dk[o] = sk[idx];
        dv[o] = sv[idx];
    }
    for (int i = tid; i < 640; i += NTPB) {
        sm[SM_W1K + i] = Wk1[i];
        sm[SM_W1V + i] = Wv1[i];
    }
}

// h pairs over 20 edges for hidden unit t (folds /sqrt(10), silu, /8)
static __device__ __forceinline__ void fc1_row(const float* ws, const float* W1s,
                                               int t, u64* h) {
    u64 acc[10];
    {
        float w = W1s[t];
        u64 wd = pk2(w, w);
        const ulonglong2* Er = (const ulonglong2*)(ws + EMB_OFF);
#pragma unroll
        for (int m = 0; m < 5; m++) {
            ulonglong2 p = Er[m];
            acc[2 * m] = mul2(wd, p.x);
            acc[2 * m + 1] = mul2(wd, p.y);
        }
    }
#pragma unroll
    for (int b = 1; b < 10; b++) {
        float w = W1s[b * 64 + t];
        u64 wd = pk2(w, w);
        const ulonglong2* Er = (const ulonglong2*)(ws + EMB_OFF + b * 24);
#pragma unroll
        for (int m = 0; m < 5; m++) {
            ulonglong2 p = Er[m];
            acc[2 * m] = f2(wd, p.x, acc[2 * m]);
            acc[2 * m + 1] = f2(wd, p.y, acc[2 * m + 1]);
        }
    }
#pragma unroll
    for (int m = 0; m < 10; m++) {
        float a0, a1;
        upk2(acc[m], a0, a1);
        a0 *= 0.31622776601683794f;
        a1 *= 0.31622776601683794f;
        h[m] = pk2(__fdividef(a0, 1.f + __expf(-a0)) * 0.125f,
                   __fdividef(a1, 1.f + __expf(-a1)) * 0.125f);
    }
}

static __device__ __forceinline__ void dupd(const float* ws, int xi, float M, u64* D) {
    u64 Md = pk2(M, M);
    const ulonglong2* Fr = (const ulonglong2*)(ws + F_OFF + xi * 24);
#pragma unroll
    for (int m = 0; m < 5; m++) {
        ulonglong2 p = Fr[m];
        D[2 * m] = f2(Md, p.x, D[2 * m]);
        D[2 * m + 1] = f2(Md, p.y, D[2 * m + 1]);
    }
}

static __device__ __forceinline__ float srow(const float* ws, int xi, const u64* hp) {
    const ulonglong2* Fr = (const ulonglong2*)(ws + F_OFF + xi * 24);
    u64 s0 = 0ULL, s1 = 0ULL;
#pragma unroll
    for (int m = 0; m < 5; m++) {
        ulonglong2 p = Fr[m];
        s0 = f2(hp[2 * m], p.x, s0);
        s1 = f2(hp[2 * m + 1], p.y, s1);
    }
    float lo, hi;
    upk2(add2(s0, s1), lo, hi);
    return lo + hi;
}

// dot8 against register q
static __device__ __forceinline__ float dot8(const u64* wk, const u64* q) {
    u64 p0 = mul2(wk[0], q[0]);
    p0 = f2(wk[1], q[1], p0);
    u64 p1 = mul2(wk[2], q[2]);
    p1 = f2(wk[3], q[3], p1);
    float lo, hi;
    upk2(add2(p0, p1), lo, hi);
    return lo + hi;
}

// dot8 against qv in smem (volatile: keep qv out of registers)
static __device__ __forceinline__ float dot8qv(u64 w0, u64 w1, u64 w2, u64 w3,
                                               unsigned qsh) {
    u64 q0, q1, q2, q3;
    asm volatile("ld.shared.v2.u64 {%0, %1}, [%2];"
                 : "=l"(q0), "=l"(q1) : "r"(qsh));
    asm volatile("ld.shared.v2.u64 {%0, %1}, [%2];"
                 : "=l"(q2), "=l"(q3) : "r"(qsh + 16));
    u64 p0 = mul2(w0, q0);
    p0 = f2(w1, q1, p0);
    u64 p1 = mul2(w2, q2);
    p1 = f2(w3, q3, p1);
    float lo, hi;
    upk2(add2(p0, p1), lo, hi);
    return lo + hi;
}

__global__ __launch_bounds__(NTPB, 1) void se3_main(
    const float* __restrict__ f, const float* __restrict__ pos,
    const float* __restrict__ Wk1, const float* __restrict__ Wk2,
    const float* __restrict__ Wv1, const float* __restrict__ Wv2,
    const int* __restrict__ edge_src, float* __restrict__ out) {
    extern __shared__ float sm[];
    const int tid = threadIdx.x;
    const int wid = tid >> 5, lane = tid & 31;
    const int n = blockIdx.x * NODES_PB + wid;
    const bool active = (n < NN);
    float* ws = sm + SM_NS + wid * NS_STR;

    // ---- setup: lanes 0-19 = edges; lanes 20-22 pack qv into scratch ----
    if (active) {
        if (lane < 20) {
            int e = lane;
            int src = edge_src[n * DEG + e];
            float dx = pos[src * 3 + 0] - pos[n * 3 + 0];
            float dy = pos[src * 3 + 1] - pos[n * 3 + 1];
            float dz = pos[src * 3 + 2] - pos[n * 3 + 2];
            float r2 = fmaf(dx, dx, fmaf(dy, dy, dz * dz));
            float ir = rsqrtf(r2);
            float r = r2 * ir;
            float uu[3] = {dx * ir, dy * ir, dz * ir};
            const float4* fp = (const float4*)(f + src * 32);
            float4 s0 = fp[0], s1 = fp[1];
            float gs[8] = {s0.x, s0.y, s0.z, s0.w, s1.x, s1.y, s1.z, s1.w};
            float gv[24];
            {
                float4 v0 = fp[2], v1 = fp[3], v2 = fp[4];
                float4 v3 = fp[5], v4 = fp[6], v5 = fp[7];
                gv[0]=v0.x; gv[1]=v0.y; gv[2]=v0.z; gv[3]=v0.w;
                gv[4]=v1.x; gv[5]=v1.y; gv[6]=v1.z; gv[7]=v1.w;
                gv[8]=v2.x; gv[9]=v2.y; gv[10]=v2.z; gv[11]=v2.w;
                gv[12]=v3.x; gv[13]=v3.y; gv[14]=v3.z; gv[15]=v3.w;
                gv[16]=v4.x; gv[17]=v4.y; gv[18]=v4.z; gv[19]=v4.w;
                gv[20]=v5.x; gv[21]=v5.y; gv[22]=v5.z; gv[23]=v5.w;
            }
            float* Ff = ws + F_OFF;
#pragma unroll
            for (int i = 0; i < 8; i++) {
                float gsi = gs[i];
                float g0 = gv[3 * i + 0], g1 = gv[3 * i + 1], g2 = gv[3 * i + 2];
                Ff[i * 24 + e] = gsi;
                Ff[(8 + i) * 24 + e] = fmaf(g0, uu[0], fmaf(g1, uu[1], g2 * uu[2]));
                Ff[(16 + i * 3 + 0) * 24 + e] = gsi * uu[0];
                Ff[(16 + i * 3 + 1) * 24 + e] = gsi * uu[1];
                Ff[(16 + i * 3 + 2) * 24 + e] = gsi * uu[2];
                Ff[(40 + i * 3 + 0) * 24 + e] = g0;
                Ff[(40 + i * 3 + 1) * 24 + e] = g1;
                Ff[(40 + i * 3 + 2) * 24 + e] = g2;
            }
            float rr = r * (11.0f / 3.5f);
#pragma unroll
            for (int b = 0; b < 10; b++) {
                float d = rr - (float)(b + 1);
                ws[EMB_OFF + b * 24 + e] = 26.66929f * ss(d + 1.f) * ss(1.f - d);
            }
            float x = 10.f * (1.f - r * (1.f / 3.5f));
            ws[LC_OFF + e] = (x > 0.f) ? -__fdividef(1.f, x) : -1e30f;
        } else if (lane < 23) {
            int c = lane - 20;
            const float* qf = g_qt + n * 32 + 8;
            u64* qd = (u64*)(ws + QV_OFF) + c * 4;
#pragma unroll
            for (int m = 0; m < 4; m++)
                qd[m] = pk2(qf[(2 * m) * 3 + c], qf[(2 * m + 1) * 3 + c]);
        }
    }
    stage_all(sm, Wk2, Wv2, Wk1, Wv1, tid);
    __syncthreads();

    const unsigned qv_sh = (unsigned)__cvta_generic_to_shared(ws + QV_OFF);
    const unsigned co_sh = (unsigned)__cvta_generic_to_shared(ws + CO_OFF);

    // ============ PASS 0: k-net -> logits -> coef (warp-independent) ============
    if (active) {
        const u64* W2s64 = (const u64*)sm;
        const float* W1s = sm + SM_W1K;
        u64 qq[4];
        {
            const u64* qsp = (const u64*)(g_qt + n * 32);
#pragma unroll
            for (int m = 0; m < 4; m++) qq[m] = qsp[m];
        }
        u64 Lacc[10];
#pragma unroll
        for (int m = 0; m < 10; m++) Lacc[m] = 0ULL;

#pragma unroll 1
        for (int half = 0; half < 2; half++) {
            int t = half * 32 + lane;
            u64 h[10], D[10];
            fc1_row(ws, W1s, t, h);
#pragma unroll
            for (int m = 0; m < 10; m++) D[m] = 0ULL;
            const u64* wrow = W2s64 + t * 129;
            // paths 0,1 (xi = pi): M[2] batches
#pragma unroll 1
            for (int g = 0; g < 8; g++) {
                float M0 = dot8(wrow + (2 * g) * 4, qq);
                float M1 = dot8(wrow + (2 * g + 1) * 4, qq);
                dupd(ws, 2 * g, M0, D);
                dupd(ws, 2 * g + 1, M1, D);
            }
            // paths 2,3: qv from smem (volatile)
#pragma unroll 1
            for (int pi = 0; pi < 16; pi++) {
                const u64* wk = wrow + 64 + pi * 4;
                u64 w0 = wk[0], w1 = wk[1], w2 = wk[2], w3 = wk[3];
                int xb = 16 + (pi >> 3) * 24 + (pi & 7) * 3;
                float sc = (pi >= 8) ? 0.5773502691896258f : 1.0f;
#pragma unroll
                for (int c = 0; c < 3; c++)
                    dupd(ws, xb + c,
                         dot8qv(w0, w1, w2, w3, qv_sh + c * 32) * sc, D);
            }
#pragma unroll
            for (int m = 0; m < 10; m++) Lacc[m] = f2(h[m], D[m], Lacc[m]);
        }
#pragma unroll
        for (int o = 16; o >= 1; o >>= 1)
#pragma unroll
            for (int m = 0; m < 10; m++)
                Lacc[m] = add2(Lacc[m], __shfl_xor_sync(0xffffffffu, Lacc[m], o));
        if (lane == 0) {
            u64* Lg = (u64*)(ws + LG_OFF);
#pragma unroll
            for (int m = 0; m < 10; m++) Lg[m] = Lacc[m];
        }
        __syncwarp();
        {
            float L = -3.0e38f;
            if (lane < 20)
                L = fmaf(0.022097086912079608f, ws[LG_OFF + lane], ws[LC_OFF + lane]);
            float M = L;
#pragma unroll
            for (int o = 16; o >= 1; o >>= 1)
                M = fmaxf(M, __shfl_xor_sync(0xffffffffu, M, o));
            float ex = (lane < 20) ? __expf(L - M) : 0.f;
            float z = bsum(ex);
            if (lane < 20)
                ws[CO_OFF + lane] = 0.25f * sqrtf(__fdividef(ex, z) + 1e-12f);
        }
        __syncwarp();
    }

    // ============ PASS 1: v-net -> outputs (no block sync needed) ============
    if (active) {
        const u64* W2s64 = (const u64*)(sm + SM_W2V);
        const float* W1s = sm + SM_W1V;
        u64 os[4] = {0ULL, 0ULL, 0ULL, 0ULL};
        u64 ov[3][4] = {};

#pragma unroll 1
        for (int half = 0; half < 2; half++) {
            int t = half * 32 + lane;
            u64 h[10];
            fc1_row(ws, W1s, t, h);
            // scale by coef from smem (volatile: keep co out of registers)
#pragma unroll
            for (int m = 0; m < 10; m++) {
                u64 cm;
                asm volatile("ld.shared.b64 %0, [%1];"
                             : "=l"(cm) : "r"(co_sh + m * 8));
                h[m] = mul2(h[m], cm);
            }
            const u64* wrow = W2s64 + t * 129;
            // paths 0,1 -> out_s: S[2] batches
#pragma unroll 1
            for (int g = 0; g < 8; g++) {
                float S0 = srow(ws, 2 * g, h);
                float S1 = srow(ws, 2 * g + 1, h);
                u64 Sd0 = pk2(S0, S0), Sd1 = pk2(S1, S1);
                const u64* wk0 = wrow + (2 * g) * 4;
                const u64* wk1 = wrow + (2 * g + 1) * 4;
#pragma unroll
                for (int r = 0; r < 4; r++) os[r] = f2(Sd0, wk0[r], os[r]);
#pragma unroll
                for (int r = 0; r < 4; r++) os[r] = f2(Sd1, wk1[r], os[r]);
            }
            // paths 2,3 -> out_v
#pragma unroll 1
            for (int pi = 0; pi < 16; pi++) {
                const u64* wk = wrow + 64 + pi * 4;
                u64 w0 = wk[0], w1 = wk[1], w2 = wk[2], w3 = wk[3];
                int xb = 16 + (pi >> 3) * 24 + (pi & 7) * 3;
                float sc = (pi < 8) ? 1.7320508075688772f : 1.0f;
#pragma unroll
                for (int c = 0; c < 3; c++) {
                    float S = srow(ws, xb + c, h) * sc;
                    u64 Sd = pk2(S, S);
                    ov[c][0] = f2(Sd, w0, ov[c][0]);
                    ov[c][1] = f2(Sd, w1, ov[c][1]);
                    ov[c][2] = f2(Sd, w2, ov[c][2]);
                    ov[c][3] = f2(Sd, w3, ov[c][3]);
                }
            }
        }
#pragma unroll
        for (int o = 16; o >= 1; o >>= 1) {
#pragma unroll
            for (int r = 0; r < 4; r++)
                os[r] = add2(os[r], __shfl_xor_sync(0xffffffffu, os[r], o));
#pragma unroll
            for (int c = 0; c < 3; c++)
#pragma unroll
                for (int r = 0; r < 4; r++)
                    ov[c][r] = add2(ov[c][r], __shfl_xor_sync(0xffffffffu, ov[c][r], o));
        }
        if (lane < 4) {
            float a, b;
            upk2(os[lane], a, b);
            out[n * 32 + 2 * lane] = a;
            out[n * 32 + 2 * lane + 1] = b;
        } else if (lane < 16) {
            int idx = lane - 4;
            int c = idx >> 2, r = idx & 3;
            float a, b;
            upk2(ov[c][r], a, b);
            out[n * 32 + 8 + (2 * r) * 3 + c] = a;
            out[n * 32 + 8 + (2 * r + 1) * 3 + c] = b;
        }
    }
}

extern "C" void kernel_launch(void* const* d_in, const int* in_sizes, int n_in,
                              void* d_out, int out_size) {
    const float* f    = (const float*)d_in[0];
    const float* pos  = (const float*)d_in[1];
    const float* Wq_s = (const float*)d_in[2];
    const float* Wq_v = (const float*)d_in[3];
    const float* Wk1  = (const float*)d_in[4];
    const float* Wk2  = (const float*)d_in[5];
    const float* Wv1  = (const float*)d_in[6];
    const float* Wv2  = (const float*)d_in[7];
    const float* Wd_s = (const float*)d_in[8];
    const float* Wd_v = (const float*)d_in[9];
    const int* esrc   = (const int*)d_in[10];
    float* out = (float*)d_out;

    cudaFuncSetAttribute(se3_main, cudaFuncAttributeMaxDynamicSharedMemorySize, SMEM_BYTES);
    k0_qt<<<64, 256>>>(f, Wq_s, Wq_v, Wd_s, Wd_v);
    se3_main<<<(NN + NODES_PB - 1) / NODES_PB, NTPB, SMEM_BYTES>>>(
        f, pos, Wk1, Wk2, Wv1, Wv2, esrc, out);
}